// round 15
// baseline (speedup 1.0000x reference)
#include <cuda_runtime.h>
#include <cstdint>

// ----------------------------------------------------------------------------
// MLPPredictor: score[e] = W * concat(h[src[e]], h[dst[e]]) + b
//   h: [N,5] f32, src/dst: [E] int64 (or int32 — detected), W: [16,10], b:[16]
//   out: [E,16] f32
//
// R15 = R12 champion (R14's stream fork FAILED: +3us graph overhead) with
//   adjacent-edge pairing: thread g handles edges (2g, 2g+1).
//   - src/dst index pairs load as one aligned ld.global.nc.v2 each
//     (4 idx LDGs -> 2; idx wavefronts halve)
//   - each thread owns a contiguous 128B output span; tail handled by
//     clamping e0 = min(2g, E-2) -> unconditional stores (dup stores at the
//     tail write identical values; benign)
//   Unchanged: fused prep -> constant-bank weights+idx flag -> main kernel,
//   32B padded rows + v8 gathers, phase-split accs, f32x2 math, 256-bit
//   stores, __launch_bounds__(256,4).
//
// Converged model: main ≈ 2 scattered lines/edge x 2.07 cyc within-LDG replay
// + stores ≈ 4.8 cyc/edge/SM ≈ 103.6us measured. At the replay-rate floor.
// ----------------------------------------------------------------------------

#define MAX_NODES 100000
__device__ __align__(32) float g_hp[MAX_NODES * 8];  // padded rows, 32B each

// Staging + constant bank: [0..79] = W pairs, [80..87] = bias pairs,
// [88] = idx64 flag.  cWB[p*10+k] = (W[2p][k], W[2p+1][k]).
__device__ unsigned long long g_wpack[89];
__constant__ unsigned long long cWB[89];

__device__ __forceinline__ unsigned long long pack2f(float lo, float hi) {
    unsigned long long v;
    asm("mov.b64 %0, {%1, %2};" : "=l"(v) : "f"(lo), "f"(hi));
    return v;
}

// Fused prep: pack h [n,5] -> g_hp [n,8]; block 0 additionally packs W/bias
// pairs and detects index width (256 hi-word samples all zero => int64).
__global__ void prep_kernel(const float* __restrict__ h,
                            const float* __restrict__ W,
                            const float* __restrict__ bias,
                            const unsigned int* __restrict__ src_raw,
                            int n_nodes) {
    if (blockIdx.x == 0) {
        int t = threadIdx.x;
        if (t < 80) {
            int p = t / 10, k = t % 10;
            g_wpack[t] = pack2f(W[(2 * p) * 10 + k], W[(2 * p + 1) * 10 + k]);
        } else if (t < 88) {
            int p = t - 80;
            g_wpack[t] = pack2f(bias[2 * p], bias[2 * p + 1]);
        } else if (t >= 96 && t < 128) {
            int l = t - 96;
            unsigned int acc = 0;
#pragma unroll
            for (int j = 0; j < 8; j++)
                acc |= src_raw[2 * (l * 8 + j) + 1];
            unsigned int any = __ballot_sync(0xffffffffu, acc != 0);
            if (l == 0) g_wpack[88] = (any == 0) ? 1ull : 0ull;
        }
    }
    int i = blockIdx.x * blockDim.x + threadIdx.x;
    if (i < n_nodes) {
        const float* r = h + (size_t)i * 5;
        float4 a = make_float4(r[0], r[1], r[2], r[3]);
        float4 b = make_float4(r[4], 0.f, 0.f, 0.f);
        float4* d = reinterpret_cast<float4*>(g_hp + (size_t)i * 8);
        d[0] = a;
        d[1] = b;
    }
}

// 32B gather from a 32B-aligned row (one scattered L1tex line-pass).
__device__ __forceinline__ void gather8(const float* p, float* r) {
    asm("ld.global.nc.v8.f32 {%0,%1,%2,%3,%4,%5,%6,%7}, [%8];"
        : "=f"(r[0]), "=f"(r[1]), "=f"(r[2]), "=f"(r[3]),
          "=f"(r[4]), "=f"(r[5]), "=f"(r[6]), "=f"(r[7])
        : "l"(p));
}

__device__ __forceinline__ void store32(float* p, const unsigned long long* a) {
    asm volatile("st.global.v4.b64 [%0], {%1,%2,%3,%4};"
                 :: "l"(p), "l"(a[0]), "l"(a[1]), "l"(a[2]), "l"(a[3])
                 : "memory");
}

__global__ __launch_bounds__(256, 4) void edge_mlp_kernel(
    const char* __restrict__ src_raw,
    const char* __restrict__ dst_raw,
    float* __restrict__ out,         // [E,16]
    unsigned E)
{
    unsigned g = blockIdx.x * 256u + threadIdx.x;
    // Adjacent pair, clamped at the tail (dup threads write identical data).
    unsigned e0 = 2u * g;
    if (e0 > E - 2u) e0 = E - 2u;   // E >= 2 guaranteed by problem size
    unsigned e1 = e0 + 1u;

    // Index width: int64 -> low words of a 16B pair; int32 -> one 8B pair.
    unsigned s0, d0, s1, d1;
    if (cWB[88] != 0) {
        unsigned long long x, y;
        asm("ld.global.nc.v2.u64 {%0,%1}, [%2];"
            : "=l"(x), "=l"(y) : "l"(src_raw + ((size_t)e0 << 3)));
        s0 = (unsigned)x; s1 = (unsigned)y;
        asm("ld.global.nc.v2.u64 {%0,%1}, [%2];"
            : "=l"(x), "=l"(y) : "l"(dst_raw + ((size_t)e0 << 3)));
        d0 = (unsigned)x; d1 = (unsigned)y;
    } else {
        asm("ld.global.nc.v2.u32 {%0,%1}, [%2];"
            : "=r"(s0), "=r"(s1) : "l"(src_raw + ((size_t)e0 << 2)));
        asm("ld.global.nc.v2.u32 {%0,%1}, [%2];"
            : "=r"(d0), "=r"(d1) : "l"(dst_raw + ((size_t)e0 << 2)));
    }

    float u0[8], v0[8], u1[8], v1[8];
    gather8(g_hp + (size_t)s0 * 8, u0);
    gather8(g_hp + (size_t)d0 * 8, v0);
    gather8(g_hp + (size_t)s1 * 8, u1);
    gather8(g_hp + (size_t)d1 * 8, v1);

    float f0[10] = {u0[0], u0[1], u0[2], u0[3], u0[4],
                    v0[0], v0[1], v0[2], v0[3], v0[4]};
    float f1[10] = {u1[0], u1[1], u1[2], u1[3], u1[4],
                    v1[0], v1[1], v1[2], v1[3], v1[4]};

    float* o0 = out + (size_t)e0 * 16;
    float* o1 = out + (size_t)e1 * 16;

    // Two phases: classes [0,8) then [8,16). 4 class-pairs per phase.
#pragma unroll
    for (int ph = 0; ph < 2; ph++) {
        const int pb = ph * 4;
        unsigned long long acc0[4], acc1[4];
#pragma unroll
        for (int p = 0; p < 4; p++) {
            acc0[p] = cWB[80 + pb + p];
            acc1[p] = cWB[80 + pb + p];
        }

#pragma unroll
        for (int j = 0; j < 5; j++) {
            const int ka = 2 * j;
            unsigned long long h0a, h0b, h1a, h1b;
            asm("mov.b64 %0, {%1, %1};" : "=l"(h0a) : "f"(f0[ka]));
            asm("mov.b64 %0, {%1, %1};" : "=l"(h0b) : "f"(f0[ka + 1]));
            asm("mov.b64 %0, {%1, %1};" : "=l"(h1a) : "f"(f1[ka]));
            asm("mov.b64 %0, {%1, %1};" : "=l"(h1b) : "f"(f1[ka + 1]));
#pragma unroll
            for (int p = 0; p < 4; p++) {
                unsigned long long wa = cWB[(pb + p) * 10 + ka];
                unsigned long long wb = cWB[(pb + p) * 10 + ka + 1];
                asm("fma.rn.f32x2 %0, %1, %2, %0;" : "+l"(acc0[p]) : "l"(wa), "l"(h0a));
                asm("fma.rn.f32x2 %0, %1, %2, %0;" : "+l"(acc0[p]) : "l"(wb), "l"(h0b));
                asm("fma.rn.f32x2 %0, %1, %2, %0;" : "+l"(acc1[p]) : "l"(wa), "l"(h1a));
                asm("fma.rn.f32x2 %0, %1, %2, %0;" : "+l"(acc1[p]) : "l"(wb), "l"(h1b));
            }
        }

        store32(o0 + ph * 8, acc0);
        store32(o1 + ph * 8, acc1);
    }
}

extern "C" void kernel_launch(void* const* d_in, const int* in_sizes, int n_in,
                              void* d_out, int out_size) {
    const float* h  = (const float*)d_in[0];
    const char* src = (const char*)d_in[1];
    const char* dst = (const char*)d_in[2];
    const float* W  = (const float*)d_in[3];
    const float* b  = (const float*)d_in[4];
    float* out = (float*)d_out;

    int n_nodes = in_sizes[0] / 5;
    unsigned E = (unsigned)in_sizes[1];

    prep_kernel<<<(n_nodes + 511) / 512, 512>>>(h, W, b,
                                                (const unsigned int*)src,
                                                n_nodes);

    // Stage packed weights + idx flag into the constant bank (D2D, capturable).
    void* wsrc = nullptr;
    cudaGetSymbolAddress(&wsrc, g_wpack);
    cudaMemcpyToSymbolAsync(cWB, wsrc, 89 * sizeof(unsigned long long), 0,
                            cudaMemcpyDeviceToDevice, 0);

    edge_mlp_kernel<<<(E + 511u) / 512u, 256>>>(src, dst, out, E);
}

// round 16
// speedup vs baseline: 1.3434x; 1.3434x over previous
#include <cuda_runtime.h>
#include <cstdint>

// ----------------------------------------------------------------------------
// MLPPredictor: score[e] = W * concat(h[src[e]], h[dst[e]]) + b
//   h: [N,5] f32, src/dst: [E] int64 (or int32 — detected), W: [16,10], b:[16]
//   out: [E,16] f32
//
// FINAL = R12 champion, restored verbatim (113.0us total, main 103.6us).
//   Structure: fused prep -> constant-bank weights+idx flag (D2D symbol copy)
//   -> main kernel with 2 edges/thread at interleaved stride 256 (KEEPS warp
//   stores line-dense — R15 proved adjacent pairing quarters store density),
//   32B padded node rows + ld.global.nc.v8 gathers (1 scattered L1tex
//   line-pass per node access), phase-split accumulators (classes 0-7 then
//   8-15), fma.rn.f32x2 packed math, 256-bit stores, launch_bounds(256,4)
//   (no reg squeeze — R6 proved spills route through the binding L1tex pipe).
//
// Converged model: main ≈ 2 scattered lines/edge x ~2.07 cyc within-LDG
// replay + stores ≈ 4.8 cyc/edge/SM ≈ 103.6us measured — the replay-rate
// floor. Falsified alternatives: 1/3 edges per thread, lane-splitting,
// persistent grid, occupancy squeeze, adjacent pairing, stream-forked prep.
// ----------------------------------------------------------------------------

#define MAX_NODES 100000
__device__ __align__(32) float g_hp[MAX_NODES * 8];  // padded rows, 32B each

// Staging + constant bank: [0..79] = W pairs, [80..87] = bias pairs,
// [88] = idx64 flag.  cWB[p*10+k] = (W[2p][k], W[2p+1][k]).
__device__ unsigned long long g_wpack[89];
__constant__ unsigned long long cWB[89];

__device__ __forceinline__ unsigned long long pack2f(float lo, float hi) {
    unsigned long long v;
    asm("mov.b64 %0, {%1, %2};" : "=l"(v) : "f"(lo), "f"(hi));
    return v;
}

// Fused prep: pack h [n,5] -> g_hp [n,8]; block 0 additionally packs W/bias
// pairs and detects index width (256 hi-word samples all zero => int64).
__global__ void prep_kernel(const float* __restrict__ h,
                            const float* __restrict__ W,
                            const float* __restrict__ bias,
                            const unsigned int* __restrict__ src_raw,
                            int n_nodes) {
    if (blockIdx.x == 0) {
        int t = threadIdx.x;
        if (t < 80) {
            int p = t / 10, k = t % 10;
            g_wpack[t] = pack2f(W[(2 * p) * 10 + k], W[(2 * p + 1) * 10 + k]);
        } else if (t < 88) {
            int p = t - 80;
            g_wpack[t] = pack2f(bias[2 * p], bias[2 * p + 1]);
        } else if (t >= 96 && t < 128) {
            int l = t - 96;
            unsigned int acc = 0;
#pragma unroll
            for (int j = 0; j < 8; j++)
                acc |= src_raw[2 * (l * 8 + j) + 1];
            unsigned int any = __ballot_sync(0xffffffffu, acc != 0);
            if (l == 0) g_wpack[88] = (any == 0) ? 1ull : 0ull;
        }
    }
    int i = blockIdx.x * blockDim.x + threadIdx.x;
    if (i < n_nodes) {
        const float* r = h + (size_t)i * 5;
        float4 a = make_float4(r[0], r[1], r[2], r[3]);
        float4 b = make_float4(r[4], 0.f, 0.f, 0.f);
        float4* d = reinterpret_cast<float4*>(g_hp + (size_t)i * 8);
        d[0] = a;
        d[1] = b;
    }
}

// 32B gather from a 32B-aligned row (one scattered L1tex line-pass).
__device__ __forceinline__ void gather8(const float* p, float* r) {
    asm("ld.global.nc.v8.f32 {%0,%1,%2,%3,%4,%5,%6,%7}, [%8];"
        : "=f"(r[0]), "=f"(r[1]), "=f"(r[2]), "=f"(r[3]),
          "=f"(r[4]), "=f"(r[5]), "=f"(r[6]), "=f"(r[7])
        : "l"(p));
}

__device__ __forceinline__ void store32(float* p, const unsigned long long* a) {
    asm volatile("st.global.v4.b64 [%0], {%1,%2,%3,%4};"
                 :: "l"(p), "l"(a[0]), "l"(a[1]), "l"(a[2]), "l"(a[3])
                 : "memory");
}

__global__ __launch_bounds__(256, 4) void edge_mlp_kernel(
    const char* __restrict__ src_raw,
    const char* __restrict__ dst_raw,
    float* __restrict__ out,         // [E,16]
    unsigned E)
{
    unsigned tid = threadIdx.x;
    unsigned e0 = blockIdx.x * 512u + tid;
    unsigned e1 = e0 + 256u;
    bool ok0 = e0 < E, ok1 = e1 < E;
    unsigned a0 = ok0 ? e0 : 0u, a1 = ok1 ? e1 : 0u;

    // Index width: int64 -> stride 8 (little-endian low word), int32 -> 4.
    unsigned shift = (cWB[88] != 0) ? 3u : 2u;
    unsigned s0 = *(const unsigned*)(src_raw + ((size_t)a0 << shift));
    unsigned d0 = *(const unsigned*)(dst_raw + ((size_t)a0 << shift));
    unsigned s1 = *(const unsigned*)(src_raw + ((size_t)a1 << shift));
    unsigned d1 = *(const unsigned*)(dst_raw + ((size_t)a1 << shift));

    float u0[8], v0[8], u1[8], v1[8];
    gather8(g_hp + (size_t)s0 * 8, u0);
    gather8(g_hp + (size_t)d0 * 8, v0);
    gather8(g_hp + (size_t)s1 * 8, u1);
    gather8(g_hp + (size_t)d1 * 8, v1);

    float f0[10] = {u0[0], u0[1], u0[2], u0[3], u0[4],
                    v0[0], v0[1], v0[2], v0[3], v0[4]};
    float f1[10] = {u1[0], u1[1], u1[2], u1[3], u1[4],
                    v1[0], v1[1], v1[2], v1[3], v1[4]};

    float* o0 = out + (size_t)e0 * 16;
    float* o1 = out + (size_t)e1 * 16;

    // Two phases: classes [0,8) then [8,16). 4 class-pairs per phase.
#pragma unroll
    for (int ph = 0; ph < 2; ph++) {
        const int pb = ph * 4;
        unsigned long long acc0[4], acc1[4];
#pragma unroll
        for (int p = 0; p < 4; p++) {
            acc0[p] = cWB[80 + pb + p];
            acc1[p] = cWB[80 + pb + p];
        }

#pragma unroll
        for (int j = 0; j < 5; j++) {
            const int ka = 2 * j;
            unsigned long long h0a, h0b, h1a, h1b;
            asm("mov.b64 %0, {%1, %1};" : "=l"(h0a) : "f"(f0[ka]));
            asm("mov.b64 %0, {%1, %1};" : "=l"(h0b) : "f"(f0[ka + 1]));
            asm("mov.b64 %0, {%1, %1};" : "=l"(h1a) : "f"(f1[ka]));
            asm("mov.b64 %0, {%1, %1};" : "=l"(h1b) : "f"(f1[ka + 1]));
#pragma unroll
            for (int p = 0; p < 4; p++) {
                unsigned long long wa = cWB[(pb + p) * 10 + ka];
                unsigned long long wb = cWB[(pb + p) * 10 + ka + 1];
                asm("fma.rn.f32x2 %0, %1, %2, %0;" : "+l"(acc0[p]) : "l"(wa), "l"(h0a));
                asm("fma.rn.f32x2 %0, %1, %2, %0;" : "+l"(acc0[p]) : "l"(wb), "l"(h0b));
                asm("fma.rn.f32x2 %0, %1, %2, %0;" : "+l"(acc1[p]) : "l"(wa), "l"(h1a));
                asm("fma.rn.f32x2 %0, %1, %2, %0;" : "+l"(acc1[p]) : "l"(wb), "l"(h1b));
            }
        }

        if (ok0) store32(o0 + ph * 8, acc0);
        if (ok1) store32(o1 + ph * 8, acc1);
    }
}

extern "C" void kernel_launch(void* const* d_in, const int* in_sizes, int n_in,
                              void* d_out, int out_size) {
    const float* h  = (const float*)d_in[0];
    const char* src = (const char*)d_in[1];
    const char* dst = (const char*)d_in[2];
    const float* W  = (const float*)d_in[3];
    const float* b  = (const float*)d_in[4];
    float* out = (float*)d_out;

    int n_nodes = in_sizes[0] / 5;
    unsigned E = (unsigned)in_sizes[1];

    prep_kernel<<<(n_nodes + 255) / 256, 256>>>(h, W, b,
                                                (const unsigned int*)src,
                                                n_nodes);

    // Stage packed weights + idx flag into the constant bank (D2D, capturable).
    void* wsrc = nullptr;
    cudaGetSymbolAddress(&wsrc, g_wpack);
    cudaMemcpyToSymbolAsync(cWB, wsrc, 89 * sizeof(unsigned long long), 0,
                            cudaMemcpyDeviceToDevice, 0);

    edge_mlp_kernel<<<(E + 511u) / 512u, 256>>>(src, dst, out, E);
}

// round 17
// speedup vs baseline: 1.3768x; 1.0249x over previous
#include <cuda_runtime.h>
#include <cstdint>

// ----------------------------------------------------------------------------
// MLPPredictor: score[e] = W * concat(h[src[e]], h[dst[e]]) + b
//   h: [N,5] f32, src/dst: [E] int64 (or int32 — detected), W: [16,10], b:[16]
//   out: [E,16] f32
//
// R17 = R12/R16 champion main kernel (UNCHANGED) + copy-node elimination:
//   prep_kernel writes the packed weights/bias/idx-flag DIRECTLY into the
//   __constant__ bank's backing memory (via cudaGetSymbolAddress pointer),
//   removing the cudaMemcpyToSymbolAsync graph node (~2.5us). Valid because
//   the constant cache is not persistent across launch boundaries (same
//   mechanism that makes cudaMemcpyToSymbol-then-launch coherent).
//
// Main kernel (converged): 2 edges/thread at interleaved stride 256 (keeps
// warp stores line-dense), 32B padded rows + v8 gathers (1 scattered L1tex
// line-pass per node access — the binding resource, ~4.8 cyc/edge/SM),
// constant-port weights, phase-split accumulators, f32x2 packed math,
// 256-bit stores, launch_bounds(256,4).
// ----------------------------------------------------------------------------

#define MAX_NODES 100000
__device__ __align__(32) float g_hp[MAX_NODES * 8];  // padded rows, 32B each

// Constant bank: [0..79] = W pairs, [80..87] = bias pairs, [88] = idx64 flag.
//   cWB[p*10 + k] = (W[2p][k], W[2p+1][k]),  cWB[80+p] = (b[2p], b[2p+1])
__constant__ unsigned long long cWB[89];

__device__ __forceinline__ unsigned long long pack2f(float lo, float hi) {
    unsigned long long v;
    asm("mov.b64 %0, {%1, %2};" : "=l"(v) : "f"(lo), "f"(hi));
    return v;
}

// Fused prep: pack h [n,5] -> g_hp [n,8]; block 0 additionally packs W/bias
// pairs + idx-width flag DIRECTLY into the constant bank's backing store.
__global__ void prep_kernel(const float* __restrict__ h,
                            const float* __restrict__ W,
                            const float* __restrict__ bias,
                            const unsigned int* __restrict__ src_raw,
                            unsigned long long* __restrict__ cwb_dst,
                            int n_nodes) {
    if (blockIdx.x == 0) {
        int t = threadIdx.x;
        if (t < 80) {
            int p = t / 10, k = t % 10;
            cwb_dst[t] = pack2f(W[(2 * p) * 10 + k], W[(2 * p + 1) * 10 + k]);
        } else if (t < 88) {
            int p = t - 80;
            cwb_dst[t] = pack2f(bias[2 * p], bias[2 * p + 1]);
        } else if (t >= 96 && t < 128) {
            int l = t - 96;
            unsigned int acc = 0;
#pragma unroll
            for (int j = 0; j < 8; j++)
                acc |= src_raw[2 * (l * 8 + j) + 1];
            unsigned int any = __ballot_sync(0xffffffffu, acc != 0);
            if (l == 0) cwb_dst[88] = (any == 0) ? 1ull : 0ull;
        }
    }
    int i = blockIdx.x * blockDim.x + threadIdx.x;
    if (i < n_nodes) {
        const float* r = h + (size_t)i * 5;
        float4 a = make_float4(r[0], r[1], r[2], r[3]);
        float4 b = make_float4(r[4], 0.f, 0.f, 0.f);
        float4* d = reinterpret_cast<float4*>(g_hp + (size_t)i * 8);
        d[0] = a;
        d[1] = b;
    }
}

// 32B gather from a 32B-aligned row (one scattered L1tex line-pass).
__device__ __forceinline__ void gather8(const float* p, float* r) {
    asm("ld.global.nc.v8.f32 {%0,%1,%2,%3,%4,%5,%6,%7}, [%8];"
        : "=f"(r[0]), "=f"(r[1]), "=f"(r[2]), "=f"(r[3]),
          "=f"(r[4]), "=f"(r[5]), "=f"(r[6]), "=f"(r[7])
        : "l"(p));
}

__device__ __forceinline__ void store32(float* p, const unsigned long long* a) {
    asm volatile("st.global.v4.b64 [%0], {%1,%2,%3,%4};"
                 :: "l"(p), "l"(a[0]), "l"(a[1]), "l"(a[2]), "l"(a[3])
                 : "memory");
}

__global__ __launch_bounds__(256, 4) void edge_mlp_kernel(
    const char* __restrict__ src_raw,
    const char* __restrict__ dst_raw,
    float* __restrict__ out,         // [E,16]
    unsigned E)
{
    unsigned tid = threadIdx.x;
    unsigned e0 = blockIdx.x * 512u + tid;
    unsigned e1 = e0 + 256u;
    bool ok0 = e0 < E, ok1 = e1 < E;
    unsigned a0 = ok0 ? e0 : 0u, a1 = ok1 ? e1 : 0u;

    // Index width: int64 -> stride 8 (little-endian low word), int32 -> 4.
    unsigned shift = (cWB[88] != 0) ? 3u : 2u;
    unsigned s0 = *(const unsigned*)(src_raw + ((size_t)a0 << shift));
    unsigned d0 = *(const unsigned*)(dst_raw + ((size_t)a0 << shift));
    unsigned s1 = *(const unsigned*)(src_raw + ((size_t)a1 << shift));
    unsigned d1 = *(const unsigned*)(dst_raw + ((size_t)a1 << shift));

    float u0[8], v0[8], u1[8], v1[8];
    gather8(g_hp + (size_t)s0 * 8, u0);
    gather8(g_hp + (size_t)d0 * 8, v0);
    gather8(g_hp + (size_t)s1 * 8, u1);
    gather8(g_hp + (size_t)d1 * 8, v1);

    float f0[10] = {u0[0], u0[1], u0[2], u0[3], u0[4],
                    v0[0], v0[1], v0[2], v0[3], v0[4]};
    float f1[10] = {u1[0], u1[1], u1[2], u1[3], u1[4],
                    v1[0], v1[1], v1[2], v1[3], v1[4]};

    float* o0 = out + (size_t)e0 * 16;
    float* o1 = out + (size_t)e1 * 16;

    // Two phases: classes [0,8) then [8,16). 4 class-pairs per phase.
#pragma unroll
    for (int ph = 0; ph < 2; ph++) {
        const int pb = ph * 4;
        unsigned long long acc0[4], acc1[4];
#pragma unroll
        for (int p = 0; p < 4; p++) {
            acc0[p] = cWB[80 + pb + p];
            acc1[p] = cWB[80 + pb + p];
        }

#pragma unroll
        for (int j = 0; j < 5; j++) {
            const int ka = 2 * j;
            unsigned long long h0a, h0b, h1a, h1b;
            asm("mov.b64 %0, {%1, %1};" : "=l"(h0a) : "f"(f0[ka]));
            asm("mov.b64 %0, {%1, %1};" : "=l"(h0b) : "f"(f0[ka + 1]));
            asm("mov.b64 %0, {%1, %1};" : "=l"(h1a) : "f"(f1[ka]));
            asm("mov.b64 %0, {%1, %1};" : "=l"(h1b) : "f"(f1[ka + 1]));
#pragma unroll
            for (int p = 0; p < 4; p++) {
                unsigned long long wa = cWB[(pb + p) * 10 + ka];
                unsigned long long wb = cWB[(pb + p) * 10 + ka + 1];
                asm("fma.rn.f32x2 %0, %1, %2, %0;" : "+l"(acc0[p]) : "l"(wa), "l"(h0a));
                asm("fma.rn.f32x2 %0, %1, %2, %0;" : "+l"(acc0[p]) : "l"(wb), "l"(h0b));
                asm("fma.rn.f32x2 %0, %1, %2, %0;" : "+l"(acc1[p]) : "l"(wa), "l"(h1a));
                asm("fma.rn.f32x2 %0, %1, %2, %0;" : "+l"(acc1[p]) : "l"(wb), "l"(h1b));
            }
        }

        if (ok0) store32(o0 + ph * 8, acc0);
        if (ok1) store32(o1 + ph * 8, acc1);
    }
}

extern "C" void kernel_launch(void* const* d_in, const int* in_sizes, int n_in,
                              void* d_out, int out_size) {
    const float* h  = (const float*)d_in[0];
    const char* src = (const char*)d_in[1];
    const char* dst = (const char*)d_in[2];
    const float* W  = (const float*)d_in[3];
    const float* b  = (const float*)d_in[4];
    float* out = (float*)d_out;

    int n_nodes = in_sizes[0] / 5;
    unsigned E = (unsigned)in_sizes[1];

    // Backing address of the constant bank (host API, not a stream op).
    void* cwb_addr = nullptr;
    cudaGetSymbolAddress(&cwb_addr, cWB);

    prep_kernel<<<(n_nodes + 255) / 256, 256>>>(
        h, W, b, (const unsigned int*)src,
        (unsigned long long*)cwb_addr, n_nodes);

    edge_mlp_kernel<<<(E + 511u) / 512u, 256>>>(src, dst, out, E);
}